// round 11
// baseline (speedup 1.0000x reference)
#include <cuda_runtime.h>
#include <cuda_bf16.h>
#include <math.h>
#include <stdint.h>

#define Nn 100000
#define Dd 512
#define Kk 400

// ---------------- scratch (device globals; no allocation allowed) ----------------
__device__ float g_E[(size_t)Nn * Kk];     // exp(C/eps) for current phase (160MB)
__device__ float g_rs[6 * Kk];             // ping-pong rowsum buffers
__device__ float g_w2[Kk];
__device__ float g_coeff[Nn * 4];
__device__ float g_upd[Kk * Dd];
__device__ float g_pn[Kk * Dd];
__device__ __nv_bfloat16 g_pbf[Kk * Dd];   // bf16 B operand (protos, then protos_new)
__device__ float g_negsum[Nn];
__device__ float g_adc[Kk * Kk];
__device__ float g_e4[Nn * 4];             // phase1 E at the 4 class protos
__device__ float g_c4[Nn * 4];             // phase2 raw cosine at the 4 class protos
__device__ float g_pconsum;

__device__ __forceinline__ uint32_t pack2(float lo, float hi) {
    uint32_t r;
    asm("cvt.rn.bf16x2.f32 %0, %1, %2;" : "=r"(r) : "f"(hi), "f"(lo));
    return r;
}
__device__ __forceinline__ float mk_alpha(float rs) {
    return 1.f / (400.f * fmaxf(rs, 1e-12f));
}

// ---------------- init ----------------
__global__ void init_kernel() {
    int i = blockIdx.x * blockDim.x + threadIdx.x;
    if (i < Kk * Dd) g_upd[i] = 0.f;
    if (i < Nn) g_negsum[i] = 0.f;
    if (i < 6 * Kk) g_rs[i] = 0.f;
    if (i < Kk) g_w2[i] = 0.f;
    if (i == 0) g_pconsum = 0.f;
}

// ---------------- fp32 -> bf16 B pre-convert ----------------
__global__ void convB_kernel(const float* __restrict__ src) {
    int i = blockIdx.x * blockDim.x + threadIdx.x;
    if (i < Kk * Dd / 4) {
        float4 v = ((const float4*)src)[i];
        reinterpret_cast<uint2*>(g_pbf)[i] = make_uint2(pack2(v.x, v.y), pack2(v.z, v.w));
    }
}

// ---------------- A-resident bf16 HMMA GEMM + fused epilogue ----------------
// C[n,k] = sum_d A[n,d]*B[k,d]. BM=128 rows/CTA resident in smem (bf16).
// 5 N-tiles of 80 cols; B chunks (80x64 bf16) via cp.async 3-stage pipeline.
// 512 thr = 16 warps: wm 0..7 (16 rows, 1 m16 tile), wn 0..1 (40 cols, 5 n8 tiles).
template <int PHASE>
__global__ void __launch_bounds__(512, 1) tgemm_kernel(
    const float* __restrict__ A, const int* __restrict__ labels,
    float* __restrict__ rowsum_out)
{
    constexpr int BM  = 128;
    constexpr int AST = 1040;             // A smem row stride (512*2 + 16 pad)
    constexpr int BST = 144;              // B smem row stride (64*2 + 16 pad)
    constexpr int ASZ = BM * AST;         // 133120
    constexpr int BBUF = 80 * BST;        // 11520
    constexpr int ST = 3;

    extern __shared__ char smc[];
    char* smA = smc;
    float* colacc = (float*)(smc + ASZ + ST * BBUF);

    const uint32_t sAu = (uint32_t)__cvta_generic_to_shared(smA);
    const uint32_t sBu = sAu + ASZ;

    const int tid = threadIdx.x;
    const int bm = blockIdx.x * BM;
    const int lane = tid & 31, wid = tid >> 5;
    const int wm = wid >> 1, wn = wid & 1;

    // ---- load + convert A tile: 128 x 512 fp32 -> bf16 smem (resident) ----
#pragma unroll 4
    for (int it = 0; it < 16; it++) {
        int slot = tid + 512 * it;        // 8192 slots
        int row = slot >> 6, c = slot & 63;
        bool okr = (bm + row) < Nn;
        const float* src = A + (size_t)(bm + row) * Dd + c * 8;
        float4 v0 = okr ? *(const float4*)src : make_float4(0.f, 0.f, 0.f, 0.f);
        float4 v1 = okr ? *(const float4*)(src + 4) : make_float4(0.f, 0.f, 0.f, 0.f);
        *(uint4*)(smA + row * AST + c * 16) =
            make_uint4(pack2(v0.x, v0.y), pack2(v0.z, v0.w),
                       pack2(v1.x, v1.y), pack2(v1.z, v1.w));
    }

    // per-thread epilogue row info
    int rr[2], lb[2];
    bool ok[2];
#pragma unroll
    for (int h = 0; h < 2; h++) {
        int r = bm + wm * 16 + h * 8 + (lane >> 2);
        rr[h] = r; ok[h] = r < Nn;
        lb[h] = ok[h] ? labels[r] : -1;
    }
    float nacc[2] = {0.f, 0.f};

    auto ldgB = [&](int nt, int kc, int st) {
        {
            int row = tid >> 3, c = tid & 7;
            uint32_t dst = sBu + st * BBUF + row * BST + c * 16;
            const __nv_bfloat16* src = g_pbf + (size_t)(nt * 80 + row) * Dd + kc * 64 + c * 8;
            asm volatile("cp.async.cg.shared.global [%0], [%1], 16;" :: "r"(dst), "l"(src));
        }
        if (tid < 128) {
            int slot = tid + 512;
            int row = slot >> 3, c = slot & 7;
            uint32_t dst = sBu + st * BBUF + row * BST + c * 16;
            const __nv_bfloat16* src = g_pbf + (size_t)(nt * 80 + row) * Dd + kc * 64 + c * 8;
            asm volatile("cp.async.cg.shared.global [%0], [%1], 16;" :: "r"(dst), "l"(src));
        }
        asm volatile("cp.async.commit_group;" ::: "memory");
    };

    float acc[5][4];

    auto compute = [&](int kc, int st) {
        const uint32_t sBb = sBu + st * BBUF;
#pragma unroll
        for (int kf = 0; kf < 4; kf++) {
            const int kk = kc * 4 + kf;
            uint32_t af[4];
            uint32_t ad = sAu + (wm * 16 + (lane & 15)) * AST + kk * 32 + (lane >> 4) * 16;
            asm volatile("ldmatrix.sync.aligned.m8n8.x4.shared.b16 {%0,%1,%2,%3},[%4];"
                : "=r"(af[0]), "=r"(af[1]), "=r"(af[2]), "=r"(af[3]) : "r"(ad));
            uint32_t bf[5][2];
            {
                const int g = lane >> 3;
                uint32_t bd = sBb + (wn * 40 + (0 + (g >> 1)) * 8 + (lane & 7)) * BST
                            + kf * 32 + (g & 1) * 16;
                asm volatile("ldmatrix.sync.aligned.m8n8.x4.shared.b16 {%0,%1,%2,%3},[%4];"
                    : "=r"(bf[0][0]), "=r"(bf[0][1]), "=r"(bf[1][0]), "=r"(bf[1][1])
                    : "r"(bd));
                uint32_t bd2 = sBb + (wn * 40 + (2 + (g >> 1)) * 8 + (lane & 7)) * BST
                             + kf * 32 + (g & 1) * 16;
                asm volatile("ldmatrix.sync.aligned.m8n8.x4.shared.b16 {%0,%1,%2,%3},[%4];"
                    : "=r"(bf[2][0]), "=r"(bf[2][1]), "=r"(bf[3][0]), "=r"(bf[3][1])
                    : "r"(bd2));
                const int lq = lane & 15;
                uint32_t bd3 = sBb + (wn * 40 + 32 + (lq & 7)) * BST
                             + kf * 32 + (lq >> 3) * 16;
                asm volatile("ldmatrix.sync.aligned.m8n8.x2.shared.b16 {%0,%1},[%2];"
                    : "=r"(bf[4][0]), "=r"(bf[4][1]) : "r"(bd3));
            }
#pragma unroll
            for (int j = 0; j < 5; j++)
                asm volatile(
                    "mma.sync.aligned.m16n8k16.row.col.f32.bf16.bf16.f32 "
                    "{%0,%1,%2,%3},{%4,%5,%6,%7},{%8,%9},{%0,%1,%2,%3};"
                    : "+f"(acc[j][0]), "+f"(acc[j][1]), "+f"(acc[j][2]), "+f"(acc[j][3])
                    : "r"(af[0]), "r"(af[1]), "r"(af[2]), "r"(af[3]),
                      "r"(bf[j][0]), "r"(bf[j][1]));
        }
    };

#pragma unroll 1
    for (int nt = 0; nt < 5; nt++) {
        ldgB(nt, 0, 0);
        ldgB(nt, 1, 1);
#pragma unroll
        for (int j = 0; j < 5; j++)
#pragma unroll
            for (int q = 0; q < 4; q++) acc[j][q] = 0.f;

#pragma unroll 1
        for (int kc = 0; kc < 8; kc++) {
            if (kc < 7) asm volatile("cp.async.wait_group 1;" ::: "memory");
            else        asm volatile("cp.async.wait_group 0;" ::: "memory");
            __syncthreads();
            if (kc + 2 < 8) ldgB(nt, kc + 2, (kc + 2) % ST);
            compute(kc, kc % ST);
        }

        // ---- fused epilogue for this 80-column tile ----
        for (int i = tid; i < 80; i += 512) colacc[i] = 0.f;
        __syncthreads();
        const int cb = nt * 80 + wn * 40;
#pragma unroll
        for (int j = 0; j < 5; j++) {
            const int c0 = cb + j * 8 + (lane & 3) * 2;
            const int km = c0 % 100;
            const int kd = c0 / 100;
            float cs0 = 0.f, cs1 = 0.f;
#pragma unroll
            for (int h = 0; h < 2; h++) {
                float v0 = acc[j][2 * h], v1 = acc[j][2 * h + 1];
                float e0, e1;
                if (PHASE == 1) {
                    e0 = __expf(20.f * v0); e1 = __expf(20.f * v1);
                } else {
                    float x0 = __expf(10.f * v0), x1 = __expf(10.f * v1);
                    if (ok[h]) nacc[h] += x0 + x1;
                    e0 = x0 * x0; e1 = x1 * x1;
                }
                if (ok[h]) {
                    int r = rr[h];
                    *(float2*)&g_E[(size_t)r * Kk + c0] = make_float2(e0, e1);
                    if (PHASE == 1) {
                        if (km == lb[h])     g_e4[r * 4 + kd] = e0;
                        if (km + 1 == lb[h]) g_e4[r * 4 + kd] = e1;
                    } else {
                        if (km == lb[h])     g_c4[r * 4 + kd] = v0;
                        if (km + 1 == lb[h]) g_c4[r * 4 + kd] = v1;
                    }
                    cs0 += e0; cs1 += e1;
                }
            }
#pragma unroll
            for (int o = 4; o <= 16; o <<= 1) {
                cs0 += __shfl_xor_sync(0xffffffffu, cs0, o);
                cs1 += __shfl_xor_sync(0xffffffffu, cs1, o);
            }
            if (lane < 4) {
                atomicAdd(&colacc[wn * 40 + j * 8 + lane * 2], cs0);
                atomicAdd(&colacc[wn * 40 + j * 8 + lane * 2 + 1], cs1);
            }
        }
        __syncthreads();
        for (int i = tid; i < 80; i += 512) atomicAdd(&rowsum_out[nt * 80 + i], colacc[i]);
        __syncthreads();
    }

    if (PHASE == 2) {
#pragma unroll
        for (int h = 0; h < 2; h++) {
            float v = nacc[h];
            v += __shfl_xor_sync(0xffffffffu, v, 1);
            v += __shfl_xor_sync(0xffffffffu, v, 2);
            if ((lane & 3) == 0 && ok[h]) atomicAdd(&g_negsum[rr[h]], v);
        }
    }
}

// ---------------- fused Sinkhorn pass: alpha from rs_in, col step + next row-sum --
__global__ void __launch_bounds__(256) sink_pass(const float* __restrict__ E,
                                                 const float* __restrict__ rs_in,
                                                 float* __restrict__ rs_out) {
    __shared__ float4 s_alpha[100];
    __shared__ float s_acc[Kk];
    for (int i = threadIdx.x; i < 100; i += 256) {
        float4 r = ((const float4*)rs_in)[i];
        s_alpha[i] = make_float4(mk_alpha(r.x), mk_alpha(r.y), mk_alpha(r.z), mk_alpha(r.w));
    }
    for (int i = threadIdx.x; i < Kk; i += 256) s_acc[i] = 0.f;
    __syncthreads();

    const int lane = threadIdx.x & 31;
    const int warp = threadIdx.x >> 5;
    const int n0 = (blockIdx.x * 8 + warp) * 8;

    float4 racc[4];
#pragma unroll
    for (int j = 0; j < 4; j++) racc[j] = make_float4(0.f, 0.f, 0.f, 0.f);

#pragma unroll 1
    for (int r = 0; r < 8; r++) {
        int n = n0 + r;
        if (n >= Nn) break;
        const float4* row = (const float4*)(E + (size_t)n * Kk);
        float4 e[4];
        float s = 0.f;
#pragma unroll
        for (int j = 0; j < 3; j++) {
            int idx = lane + 32 * j;
            e[j] = row[idx];
            float4 a = s_alpha[idx];
            s = fmaf(e[j].x, a.x, s); s = fmaf(e[j].y, a.y, s);
            s = fmaf(e[j].z, a.z, s); s = fmaf(e[j].w, a.w, s);
        }
        e[3] = make_float4(0.f, 0.f, 0.f, 0.f);
        if (lane < 4) {
            int idx = lane + 96;
            e[3] = row[idx];
            float4 a = s_alpha[idx];
            s = fmaf(e[3].x, a.x, s); s = fmaf(e[3].y, a.y, s);
            s = fmaf(e[3].z, a.z, s); s = fmaf(e[3].w, a.w, s);
        }
#pragma unroll
        for (int o = 16; o; o >>= 1) s += __shfl_xor_sync(0xffffffffu, s, o);
        float beta = 1.f / ((float)Nn * fmaxf(s, 1e-30f));
#pragma unroll
        for (int j = 0; j < 4; j++) {
            racc[j].x = fmaf(e[j].x, beta, racc[j].x);
            racc[j].y = fmaf(e[j].y, beta, racc[j].y);
            racc[j].z = fmaf(e[j].z, beta, racc[j].z);
            racc[j].w = fmaf(e[j].w, beta, racc[j].w);
        }
    }
#pragma unroll
    for (int j = 0; j < 4; j++) {
        int idx = lane + 32 * j;
        if (idx < 100) {
            atomicAdd(&s_acc[4 * idx + 0], racc[j].x);
            atomicAdd(&s_acc[4 * idx + 1], racc[j].y);
            atomicAdd(&s_acc[4 * idx + 2], racc[j].z);
            atomicAdd(&s_acc[4 * idx + 3], racc[j].w);
        }
    }
    __syncthreads();
    for (int i = threadIdx.x; i < Kk; i += 256) atomicAdd(&rs_out[i], s_acc[i]);
}

// ---------------- per-sample transport coeffs + column sums w2 ----------------
__global__ void coeff_kernel(const int* __restrict__ labels,
                             const float* __restrict__ rs_in) {
    __shared__ float sacc[Kk];
    for (int i = threadIdx.x; i < Kk; i += blockDim.x) sacc[i] = 0.f;
    __syncthreads();
    int n = blockIdx.x * blockDim.x + threadIdx.x;
    int l = 0;
    float c4[4] = {0.f, 0.f, 0.f, 0.f};
    if (n < Nn) {
        l = labels[n];
        float q[4], s = 0.f;
        float4 e4 = *(const float4*)&g_e4[n * 4];
        float ev[4] = {e4.x, e4.y, e4.z, e4.w};
#pragma unroll
        for (int p = 0; p < 4; p++) {
            q[p] = mk_alpha(rs_in[l + 100 * p]) * ev[p];
            s += q[p];
        }
        float inv = 1.f / fmaxf(s, 1e-30f);
#pragma unroll
        for (int p = 0; p < 4; p++) {
            float c = q[p] * inv;
            c4[p] = c;
            g_coeff[n * 4 + p] = c;
        }
#pragma unroll
        for (int p = 0; p < 4; p++) atomicAdd(&sacc[l + 100 * p], c4[p]);
    }
    __syncthreads();
    for (int i = threadIdx.x; i < Kk; i += blockDim.x) atomicAdd(&g_w2[i], sacc[i]);
}

// ---------------- scatter: upd[k,d] += (coeff/w2[k]) * f[n,d] ----------------
__global__ void __launch_bounds__(256) scatter_kernel(const float* __restrict__ feats,
                                                      const int* __restrict__ labels,
                                                      int nchunks) {
    extern __shared__ float sm[];
    float* acc = sm;               // 400*64
    float* winv = sm + 400 * 64;   // 400
    const int tid = threadIdx.x;
    for (int i = tid; i < 400 * 64; i += 256) acc[i] = 0.f;
    for (int i = tid; i < Kk; i += 256) winv[i] = 1.f / fmaxf(g_w2[i], 1e-12f);
    __syncthreads();

    const int d = tid & 63;
    const int sub = tid >> 6;
    const int d0 = blockIdx.x * 64;
    const int CH = (Nn + nchunks - 1) / nchunks;
    const int nb = blockIdx.y * CH;
    const int ne = (nb + CH < Nn) ? (nb + CH) : Nn;

    for (int n = nb; n < ne; n++) {
        int l = labels[n];
        float f = feats[(size_t)n * Dd + d0 + d];
        int k = l + 100 * sub;
        float c = g_coeff[n * 4 + sub] * winv[k];
        acc[k * 64 + d] += c * f;
    }
    __syncthreads();
    for (int i = tid; i < 400 * 64; i += 256)
        atomicAdd(&g_upd[(i >> 6) * Dd + d0 + (i & 63)], acc[i]);
}

// ---------------- protos_new = l2norm(0.99*protos + 0.01*upd); fp32 + bf16 ------
__global__ void pnew_kernel(const float* __restrict__ protos) {
    int k = blockIdx.x;
    int tid = threadIdx.x;  // 128
    float v[4];
    float ss = 0.f;
#pragma unroll
    for (int j = 0; j < 4; j++) {
        int di = tid + 128 * j;
        float x = 0.99f * protos[k * Dd + di] + 0.01f * g_upd[k * Dd + di];
        v[j] = x;
        ss += x * x;
    }
    __shared__ float red[4];
#pragma unroll
    for (int o = 16; o; o >>= 1) ss += __shfl_xor_sync(0xffffffffu, ss, o);
    if ((tid & 31) == 0) red[tid >> 5] = ss;
    __syncthreads();
    float tot = red[0] + red[1] + red[2] + red[3];
    float inv = 1.f / fmaxf(sqrtf(tot), 1e-12f);
#pragma unroll
    for (int j = 0; j < 4; j++) {
        float y = v[j] * inv;
        g_pn[k * Dd + tid + 128 * j] = y;
        g_pbf[k * Dd + tid + 128 * j] = __float2bfloat16(y);
    }
}

// ---------------- small SIMT GEMM for adc = pn @ pn.T (400x400x512) ----------
__global__ void __launch_bounds__(256) adc_gemm(const float* __restrict__ A,
                                                const float* __restrict__ Bm,
                                                float* __restrict__ Cb, int Mr, int Nc)
{
    __shared__ float As[16][128];
    __shared__ float Bs[16][64];
    const int tid = threadIdx.x;
    const int bm = blockIdx.y * 128;
    const int bn = blockIdx.x * 64;
    const int tx = tid & 15;
    const int ty = tid >> 4;

    float acc[8][4];
#pragma unroll
    for (int i = 0; i < 8; i++)
#pragma unroll
        for (int j = 0; j < 4; j++) acc[i][j] = 0.f;

    const int alr = tid >> 1, alc = (tid & 1) * 8;
    const int blr = tid >> 2, blc = (tid & 3) * 4;
    const bool arow_ok = (bm + alr) < Mr;
    const bool brow_ok = (bn + blr) < Nc;
    const float* Aptr = A + (size_t)(bm + alr) * Dd + alc;
    const float* Bptr = Bm + (size_t)(bn + blr) * Dd + blc;

    for (int dk = 0; dk < Dd; dk += 16) {
        float4 a0 = {0,0,0,0}, a1 = {0,0,0,0}, b0 = {0,0,0,0};
        if (arow_ok) {
            a0 = *(const float4*)(Aptr + dk);
            a1 = *(const float4*)(Aptr + dk + 4);
        }
        if (brow_ok) b0 = *(const float4*)(Bptr + dk);
        As[alc + 0][alr] = a0.x; As[alc + 1][alr] = a0.y;
        As[alc + 2][alr] = a0.z; As[alc + 3][alr] = a0.w;
        As[alc + 4][alr] = a1.x; As[alc + 5][alr] = a1.y;
        As[alc + 6][alr] = a1.z; As[alc + 7][alr] = a1.w;
        Bs[blc + 0][blr] = b0.x; Bs[blc + 1][blr] = b0.y;
        Bs[blc + 2][blr] = b0.z; Bs[blc + 3][blr] = b0.w;
        __syncthreads();
#pragma unroll
        for (int dd = 0; dd < 16; dd++) {
            float4 av0 = *(const float4*)&As[dd][ty * 8];
            float4 av1 = *(const float4*)&As[dd][ty * 8 + 4];
            float4 bv  = *(const float4*)&Bs[dd][tx * 4];
            float ar[8] = {av0.x, av0.y, av0.z, av0.w, av1.x, av1.y, av1.z, av1.w};
            float br[4] = {bv.x, bv.y, bv.z, bv.w};
#pragma unroll
            for (int i = 0; i < 8; i++)
#pragma unroll
                for (int j = 0; j < 4; j++)
                    acc[i][j] = fmaf(ar[i], br[j], acc[i][j]);
        }
        __syncthreads();
    }
#pragma unroll
    for (int i = 0; i < 8; i++) {
        int n = bm + ty * 8 + i;
        if (n >= Mr) continue;
#pragma unroll
        for (int j = 0; j < 4; j++) {
            int k = bn + tx * 4 + j;
            if (k < Nc) Cb[(size_t)n * Kk + k] = acc[i][j];
        }
    }
}

// ---------------- proto contrast: one block per proto row ----------------
__global__ void pcon_kernel() {
    int k = blockIdx.x;
    int tid = threadIdx.x;  // 128
    const float* row = g_adc + k * Kk;
    __shared__ float rbuf[4];
    __shared__ float mxs;

    float mx = -1e30f;
    for (int j = tid; j < Kk; j += 128) mx = fmaxf(mx, 2.f * row[j]);
#pragma unroll
    for (int o = 16; o; o >>= 1) mx = fmaxf(mx, __shfl_xor_sync(0xffffffffu, mx, o));
    if ((tid & 31) == 0) rbuf[tid >> 5] = mx;
    __syncthreads();
    if (tid == 0) mxs = fmaxf(fmaxf(rbuf[0], rbuf[1]), fmaxf(rbuf[2], rbuf[3]));
    __syncthreads();
    mx = mxs;

    float se = 0.f, pp = 0.f;
    int cls = k % 100;
    for (int j = tid; j < Kk; j += 128) {
        float lg = 2.f * row[j] - mx;
        if (j != k) {
            se += __expf(lg);
            if (j % 100 == cls) pp += lg;
        }
    }
#pragma unroll
    for (int o = 16; o; o >>= 1) {
        se += __shfl_xor_sync(0xffffffffu, se, o);
        pp += __shfl_xor_sync(0xffffffffu, pp, o);
    }
    __shared__ float sbuf[4], pbuf[4];
    if ((tid & 31) == 0) { sbuf[tid >> 5] = se; pbuf[tid >> 5] = pp; }
    __syncthreads();
    if (tid == 0) {
        float sT = sbuf[0] + sbuf[1] + sbuf[2] + sbuf[3];
        float pT = pbuf[0] + pbuf[1] + pbuf[2] + pbuf[3];
        atomicAdd(&g_pconsum, pT * (1.f / 3.f) - logf(sT));
    }
}

// ---------------- final per-sample loss ----------------
__global__ void final_kernel(const int* __restrict__ labels,
                             const float* __restrict__ rs_in,
                             float* __restrict__ out) {
    int n = blockIdx.x * blockDim.x + threadIdx.x;
    if (n >= Nn) return;
    int l = labels[n];
    float4 cc = *(const float4*)&g_c4[n * 4];
    float cv[4] = {cc.x, cc.y, cc.z, cc.w};
    float num = 0.f, den = 0.f;
#pragma unroll
    for (int p = 0; p < 4; p++) {
        float c = cv[p];
        float q = mk_alpha(rs_in[l + 100 * p]) * __expf(20.f * c);
        num += q * (10.f * c);
        den += q;
    }
    float pos = num / fmaxf(den, 1e-30f);
    float neg = logf(g_negsum[n]);
    float pcon = -g_pconsum * (1.f / 400.f);
    out[n] = -(pos - neg) + pcon;
}

// ---------------- launch ----------------
extern "C" void kernel_launch(void* const* d_in, const int* in_sizes, int n_in,
                              void* d_out, int out_size) {
    const float* feats  = (const float*)d_in[0];
    const float* protos = (const float*)d_in[1];
    const int*   labels = (const int*)d_in[2];
    float* out = (float*)d_out;

    float *pE, *pPN, *pADC, *pRS;
    cudaGetSymbolAddress((void**)&pE,  g_E);
    cudaGetSymbolAddress((void**)&pPN, g_pn);
    cudaGetSymbolAddress((void**)&pADC, g_adc);
    cudaGetSymbolAddress((void**)&pRS, g_rs);

    const int SMEM_SCATTER = (400 * 64 + 400) * 4;
    cudaFuncSetAttribute(scatter_kernel, cudaFuncAttributeMaxDynamicSharedMemorySize,
                         SMEM_SCATTER);
    const int TG_SMEM = 128 * 1040 + 3 * 11520 + 320;   // 168000
    cudaFuncSetAttribute(tgemm_kernel<1>, cudaFuncAttributeMaxDynamicSharedMemorySize, TG_SMEM);
    cudaFuncSetAttribute(tgemm_kernel<2>, cudaFuncAttributeMaxDynamicSharedMemorySize, TG_SMEM);

    init_kernel<<<(Kk * Dd + 255) / 256, 256>>>();
    convB_kernel<<<(Kk * Dd / 4 + 255) / 256, 256>>>(protos);

    const int NB = (Nn + 127) / 128;   // 782

    // ---------- phase 1: E1 = exp(20*feats@protos^T), rowsum -> rs0, e4 ----------
    tgemm_kernel<1><<<NB, 512, TG_SMEM>>>(feats, labels, pRS + 0 * Kk);
    sink_pass<<<(Nn + 63) / 64, 256>>>(pE, pRS + 0 * Kk, pRS + 1 * Kk);
    sink_pass<<<(Nn + 63) / 64, 256>>>(pE, pRS + 1 * Kk, pRS + 2 * Kk);

    coeff_kernel<<<(Nn + 255) / 256, 256>>>(labels, pRS + 2 * Kk);
    {
        dim3 gs(8, 64);
        scatter_kernel<<<gs, 256, SMEM_SCATTER>>>(feats, labels, 64);
    }
    pnew_kernel<<<Kk, 128>>>(protos);   // writes g_pn (fp32) + g_pbf (bf16)

    // ---------- phase 2: E2, c4, negsum vs protos_new ----------
    tgemm_kernel<2><<<NB, 512, TG_SMEM>>>(feats, labels, pRS + 3 * Kk);
    sink_pass<<<(Nn + 63) / 64, 256>>>(pE, pRS + 3 * Kk, pRS + 4 * Kk);
    sink_pass<<<(Nn + 63) / 64, 256>>>(pE, pRS + 4 * Kk, pRS + 5 * Kk);

    // ---------- proto contrast ----------
    {
        dim3 ga((Kk + 63) / 64, (Kk + 127) / 128);
        adc_gemm<<<ga, 256>>>(pPN, pPN, pADC, Kk, Kk);
    }
    pcon_kernel<<<Kk, 128>>>();

    final_kernel<<<(Nn + 255) / 256, 256>>>(labels, pRS + 5 * Kk, out);
}

// round 13
// speedup vs baseline: 1.0586x; 1.0586x over previous
#include <cuda_runtime.h>
#include <cuda_bf16.h>
#include <math.h>
#include <stdint.h>

#define Nn 100000
#define Dd 512
#define Kk 400

// ---------------- scratch (device globals; no allocation allowed) ----------------
__device__ __nv_bfloat16 g_E[(size_t)Nn * Kk];  // exp(C/eps), bf16 (80MB)
__device__ float g_rs[6 * Kk];             // ping-pong rowsum buffers
__device__ float g_w2[Kk];
__device__ float g_coeff[Nn * 4];
__device__ float g_upd[Kk * Dd];
__device__ float g_pn[Kk * Dd];
__device__ __nv_bfloat16 g_pbf[Kk * Dd];   // bf16 B operand (protos, then protos_new)
__device__ float g_negsum[Nn];
__device__ float g_adc[Kk * Kk];
__device__ float g_e4[Nn * 4];             // phase1 E at the 4 class protos (fp32)
__device__ float g_c4[Nn * 4];             // phase2 raw cosine at the 4 class protos
__device__ float g_pconsum;

__device__ __forceinline__ uint32_t pack2(float lo, float hi) {
    uint32_t r;
    asm("cvt.rn.bf16x2.f32 %0, %1, %2;" : "=r"(r) : "f"(hi), "f"(lo));
    return r;
}
__device__ __forceinline__ float mk_alpha(float rs) {
    return 1.f / (400.f * fmaxf(rs, 1e-12f));
}
// bf16 (packed low/high halves of u32) -> fp32 by shifting into exponent position
__device__ __forceinline__ float bf_lo(uint32_t u) { return __uint_as_float(u << 16); }
__device__ __forceinline__ float bf_hi(uint32_t u) { return __uint_as_float(u & 0xffff0000u); }

// ---------------- init ----------------
__global__ void init_kernel() {
    int i = blockIdx.x * blockDim.x + threadIdx.x;
    if (i < Kk * Dd) g_upd[i] = 0.f;
    if (i < Nn) g_negsum[i] = 0.f;
    if (i < 6 * Kk) g_rs[i] = 0.f;
    if (i < Kk) g_w2[i] = 0.f;
    if (i == 0) g_pconsum = 0.f;
}

// ---------------- fp32 -> bf16 B pre-convert ----------------
__global__ void convB_kernel(const float* __restrict__ src) {
    int i = blockIdx.x * blockDim.x + threadIdx.x;
    if (i < Kk * Dd / 4) {
        float4 v = ((const float4*)src)[i];
        reinterpret_cast<uint2*>(g_pbf)[i] = make_uint2(pack2(v.x, v.y), pack2(v.z, v.w));
    }
}

// ---------------- A-resident bf16 HMMA GEMM + fused epilogue ----------------
// C[n,k] = sum_d A[n,d]*B[k,d]. BM=64 rows/CTA resident in smem (bf16), 2 CTAs/SM.
// 5 N-tiles of 80 cols; B chunks (80x64 bf16) via cp.async 3-stage pipeline.
// 256 thr = 8 warps: wm 0..3 (16 rows, 1 m16 tile), wn 0..1 (40 cols, 5 n8 tiles).
template <int PHASE>
__global__ void __launch_bounds__(256, 2) tgemm_kernel(
    const float* __restrict__ A, const int* __restrict__ labels,
    float* __restrict__ rowsum_out)
{
    constexpr int BM  = 64;
    constexpr int AST = 1040;             // A smem row stride (512*2 + 16 pad)
    constexpr int BST = 144;              // B smem row stride (64*2 + 16 pad)
    constexpr int ASZ = BM * AST;         // 66560
    constexpr int BBUF = 80 * BST;        // 11520
    constexpr int ST = 3;

    extern __shared__ char smc[];
    char* smA = smc;
    float* colacc = (float*)(smc + ASZ + ST * BBUF);

    const uint32_t sAu = (uint32_t)__cvta_generic_to_shared(smA);
    const uint32_t sBu = sAu + ASZ;

    const int tid = threadIdx.x;
    const int bm = blockIdx.x * BM;
    const int lane = tid & 31, wid = tid >> 5;
    const int wm = wid >> 1, wn = wid & 1;

    // ---- load + convert A tile: 64 x 512 fp32 -> bf16 smem (resident) ----
#pragma unroll 4
    for (int it = 0; it < 16; it++) {
        int slot = tid + 256 * it;        // 4096 slots
        int row = slot >> 6, c = slot & 63;
        bool okr = (bm + row) < Nn;
        const float* src = A + (size_t)(bm + row) * Dd + c * 8;
        float4 v0 = okr ? *(const float4*)src : make_float4(0.f, 0.f, 0.f, 0.f);
        float4 v1 = okr ? *(const float4*)(src + 4) : make_float4(0.f, 0.f, 0.f, 0.f);
        *(uint4*)(smA + row * AST + c * 16) =
            make_uint4(pack2(v0.x, v0.y), pack2(v0.z, v0.w),
                       pack2(v1.x, v1.y), pack2(v1.z, v1.w));
    }

    // per-thread epilogue row info
    int rr[2], lb[2];
    bool ok[2];
#pragma unroll
    for (int h = 0; h < 2; h++) {
        int r = bm + wm * 16 + h * 8 + (lane >> 2);
        rr[h] = r; ok[h] = r < Nn;
        lb[h] = ok[h] ? labels[r] : -1;
    }
    float nacc[2] = {0.f, 0.f};

    auto ldgB = [&](int nt, int kc, int st) {
#pragma unroll
        for (int it = 0; it < 3; it++) {
            int slot = tid + 256 * it;    // 640 slots: 80 rows x 8 x 16B
            if (slot < 640) {
                int row = slot >> 3, c = slot & 7;
                uint32_t dst = sBu + st * BBUF + row * BST + c * 16;
                const __nv_bfloat16* src =
                    g_pbf + (size_t)(nt * 80 + row) * Dd + kc * 64 + c * 8;
                asm volatile("cp.async.cg.shared.global [%0], [%1], 16;"
                             :: "r"(dst), "l"(src));
            }
        }
        asm volatile("cp.async.commit_group;" ::: "memory");
    };

    float acc[5][4];

    auto compute = [&](int kc, int st) {
        const uint32_t sBb = sBu + st * BBUF;
#pragma unroll
        for (int kf = 0; kf < 4; kf++) {
            const int kk = kc * 4 + kf;
            uint32_t af[4];
            uint32_t ad = sAu + (wm * 16 + (lane & 15)) * AST + kk * 32 + (lane >> 4) * 16;
            asm volatile("ldmatrix.sync.aligned.m8n8.x4.shared.b16 {%0,%1,%2,%3},[%4];"
                : "=r"(af[0]), "=r"(af[1]), "=r"(af[2]), "=r"(af[3]) : "r"(ad));
            uint32_t bf[5][2];
            {
                const int g = lane >> 3;
                uint32_t bd = sBb + (wn * 40 + (0 + (g >> 1)) * 8 + (lane & 7)) * BST
                            + kf * 32 + (g & 1) * 16;
                asm volatile("ldmatrix.sync.aligned.m8n8.x4.shared.b16 {%0,%1,%2,%3},[%4];"
                    : "=r"(bf[0][0]), "=r"(bf[0][1]), "=r"(bf[1][0]), "=r"(bf[1][1])
                    : "r"(bd));
                uint32_t bd2 = sBb + (wn * 40 + (2 + (g >> 1)) * 8 + (lane & 7)) * BST
                             + kf * 32 + (g & 1) * 16;
                asm volatile("ldmatrix.sync.aligned.m8n8.x4.shared.b16 {%0,%1,%2,%3},[%4];"
                    : "=r"(bf[2][0]), "=r"(bf[2][1]), "=r"(bf[3][0]), "=r"(bf[3][1])
                    : "r"(bd2));
                const int lq = lane & 15;
                uint32_t bd3 = sBb + (wn * 40 + 32 + (lq & 7)) * BST
                             + kf * 32 + (lq >> 3) * 16;
                asm volatile("ldmatrix.sync.aligned.m8n8.x2.shared.b16 {%0,%1},[%2];"
                    : "=r"(bf[4][0]), "=r"(bf[4][1]) : "r"(bd3));
            }
#pragma unroll
            for (int j = 0; j < 5; j++)
                asm volatile(
                    "mma.sync.aligned.m16n8k16.row.col.f32.bf16.bf16.f32 "
                    "{%0,%1,%2,%3},{%4,%5,%6,%7},{%8,%9},{%0,%1,%2,%3};"
                    : "+f"(acc[j][0]), "+f"(acc[j][1]), "+f"(acc[j][2]), "+f"(acc[j][3])
                    : "r"(af[0]), "r"(af[1]), "r"(af[2]), "r"(af[3]),
                      "r"(bf[j][0]), "r"(bf[j][1]));
        }
    };

#pragma unroll 1
    for (int nt = 0; nt < 5; nt++) {
        ldgB(nt, 0, 0);
        ldgB(nt, 1, 1);
#pragma unroll
        for (int j = 0; j < 5; j++)
#pragma unroll
            for (int q = 0; q < 4; q++) acc[j][q] = 0.f;

#pragma unroll 1
        for (int kc = 0; kc < 8; kc++) {
            if (kc < 7) asm volatile("cp.async.wait_group 1;" ::: "memory");
            else        asm volatile("cp.async.wait_group 0;" ::: "memory");
            __syncthreads();
            if (kc + 2 < 8) ldgB(nt, kc + 2, (kc + 2) % ST);
            compute(kc, kc % ST);
        }

        // ---- fused epilogue for this 80-column tile ----
        for (int i = tid; i < 80; i += 256) colacc[i] = 0.f;
        __syncthreads();
        const int cb = nt * 80 + wn * 40;
#pragma unroll
        for (int j = 0; j < 5; j++) {
            const int c0 = cb + j * 8 + (lane & 3) * 2;
            const int km = c0 % 100;
            const int kd = c0 / 100;
            float cs0 = 0.f, cs1 = 0.f;
#pragma unroll
            for (int h = 0; h < 2; h++) {
                float v0 = acc[j][2 * h], v1 = acc[j][2 * h + 1];
                float e0, e1;
                if (PHASE == 1) {
                    e0 = __expf(20.f * v0); e1 = __expf(20.f * v1);
                } else {
                    float x0 = __expf(10.f * v0), x1 = __expf(10.f * v1);
                    if (ok[h]) nacc[h] += x0 + x1;
                    e0 = x0 * x0; e1 = x1 * x1;
                }
                if (ok[h]) {
                    int r = rr[h];
                    *(uint32_t*)&g_E[(size_t)r * Kk + c0] = pack2(e0, e1);
                    if (PHASE == 1) {
                        if (km == lb[h])     g_e4[r * 4 + kd] = e0;
                        if (km + 1 == lb[h]) g_e4[r * 4 + kd] = e1;
                    } else {
                        if (km == lb[h])     g_c4[r * 4 + kd] = v0;
                        if (km + 1 == lb[h]) g_c4[r * 4 + kd] = v1;
                    }
                    cs0 += e0; cs1 += e1;
                }
            }
#pragma unroll
            for (int o = 4; o <= 16; o <<= 1) {
                cs0 += __shfl_xor_sync(0xffffffffu, cs0, o);
                cs1 += __shfl_xor_sync(0xffffffffu, cs1, o);
            }
            if (lane < 4) {
                atomicAdd(&colacc[wn * 40 + j * 8 + lane * 2], cs0);
                atomicAdd(&colacc[wn * 40 + j * 8 + lane * 2 + 1], cs1);
            }
        }
        __syncthreads();
        for (int i = tid; i < 80; i += 256) atomicAdd(&rowsum_out[nt * 80 + i], colacc[i]);
        __syncthreads();
    }

    if (PHASE == 2) {
#pragma unroll
        for (int h = 0; h < 2; h++) {
            float v = nacc[h];
            v += __shfl_xor_sync(0xffffffffu, v, 1);
            v += __shfl_xor_sync(0xffffffffu, v, 2);
            if ((lane & 3) == 0 && ok[h]) atomicAdd(&g_negsum[rr[h]], v);
        }
    }
}

// ---------------- fused Sinkhorn pass over bf16 E ----------
// alpha from rs_in; per row: s = sum_k E*alpha; beta = 1/(N*s); rs_out[k] += E*beta
__global__ void __launch_bounds__(256) sink_pass(const __nv_bfloat16* __restrict__ E,
                                                 const float* __restrict__ rs_in,
                                                 float* __restrict__ rs_out) {
    __shared__ float s_alpha[Kk];
    __shared__ float s_acc[Kk];
    for (int i = threadIdx.x; i < Kk; i += 256) {
        s_alpha[i] = mk_alpha(rs_in[i]);
        s_acc[i] = 0.f;
    }
    __syncthreads();

    const int lane = threadIdx.x & 31;
    const int warp = threadIdx.x >> 5;
    const int n0 = (blockIdx.x * 8 + warp) * 8;

    // racc[j][t]: column (lane+32j)*4+t
    float racc[4][4];
#pragma unroll
    for (int j = 0; j < 4; j++)
#pragma unroll
        for (int t = 0; t < 4; t++) racc[j][t] = 0.f;

#pragma unroll 1
    for (int r = 0; r < 8; r++) {
        int n = n0 + r;
        if (n >= Nn) break;
        const uint2* row = (const uint2*)(E + (size_t)n * Kk);  // 100 x (4 bf16)
        uint2 u[4];
        float s = 0.f;
        float ev[4][4];
#pragma unroll
        for (int j = 0; j < 4; j++) {
            int idx = lane + 32 * j;
            bool valid = (j < 3) || (lane < 4);
            u[j] = valid ? row[idx] : make_uint2(0u, 0u);
            ev[j][0] = bf_lo(u[j].x); ev[j][1] = bf_hi(u[j].x);
            ev[j][2] = bf_lo(u[j].y); ev[j][3] = bf_hi(u[j].y);
            if (valid) {
#pragma unroll
                for (int t = 0; t < 4; t++)
                    s = fmaf(ev[j][t], s_alpha[idx * 4 + t], s);
            }
        }
#pragma unroll
        for (int o = 16; o; o >>= 1) s += __shfl_xor_sync(0xffffffffu, s, o);
        float beta = 1.f / ((float)Nn * fmaxf(s, 1e-30f));
#pragma unroll
        for (int j = 0; j < 4; j++)
#pragma unroll
            for (int t = 0; t < 4; t++)
                racc[j][t] = fmaf(ev[j][t], beta, racc[j][t]);
    }
#pragma unroll
    for (int j = 0; j < 4; j++) {
        int idx = lane + 32 * j;
        if ((j < 3) || (lane < 4)) {
#pragma unroll
            for (int t = 0; t < 4; t++)
                atomicAdd(&s_acc[idx * 4 + t], racc[j][t]);
        }
    }
    __syncthreads();
    for (int i = threadIdx.x; i < Kk; i += 256) atomicAdd(&rs_out[i], s_acc[i]);
}

// ---------------- per-sample transport coeffs + column sums w2 ----------------
__global__ void coeff_kernel(const int* __restrict__ labels,
                             const float* __restrict__ rs_in) {
    __shared__ float sacc[Kk];
    for (int i = threadIdx.x; i < Kk; i += blockDim.x) sacc[i] = 0.f;
    __syncthreads();
    int n = blockIdx.x * blockDim.x + threadIdx.x;
    int l = 0;
    float c4[4] = {0.f, 0.f, 0.f, 0.f};
    if (n < Nn) {
        l = labels[n];
        float q[4], s = 0.f;
        float4 e4 = *(const float4*)&g_e4[n * 4];
        float ev[4] = {e4.x, e4.y, e4.z, e4.w};
#pragma unroll
        for (int p = 0; p < 4; p++) {
            q[p] = mk_alpha(rs_in[l + 100 * p]) * ev[p];
            s += q[p];
        }
        float inv = 1.f / fmaxf(s, 1e-30f);
#pragma unroll
        for (int p = 0; p < 4; p++) {
            float c = q[p] * inv;
            c4[p] = c;
            g_coeff[n * 4 + p] = c;
        }
#pragma unroll
        for (int p = 0; p < 4; p++) atomicAdd(&sacc[l + 100 * p], c4[p]);
    }
    __syncthreads();
    for (int i = threadIdx.x; i < Kk; i += blockDim.x) atomicAdd(&g_w2[i], sacc[i]);
}

// ---------------- scatter: upd[k,d] += (coeff/w2[k]) * f[n,d] ----------------
__global__ void __launch_bounds__(256) scatter_kernel(const float* __restrict__ feats,
                                                      const int* __restrict__ labels,
                                                      int nchunks) {
    extern __shared__ float sm[];
    float* acc = sm;               // 400*64
    float* winv = sm + 400 * 64;   // 400
    const int tid = threadIdx.x;
    for (int i = tid; i < 400 * 64; i += 256) acc[i] = 0.f;
    for (int i = tid; i < Kk; i += 256) winv[i] = 1.f / fmaxf(g_w2[i], 1e-12f);
    __syncthreads();

    const int d = tid & 63;
    const int sub = tid >> 6;
    const int d0 = blockIdx.x * 64;
    const int CH = (Nn + nchunks - 1) / nchunks;
    const int nb = blockIdx.y * CH;
    const int ne = (nb + CH < Nn) ? (nb + CH) : Nn;

    for (int n = nb; n < ne; n++) {
        int l = labels[n];
        float f = feats[(size_t)n * Dd + d0 + d];
        int k = l + 100 * sub;
        float c = g_coeff[n * 4 + sub] * winv[k];
        acc[k * 64 + d] += c * f;
    }
    __syncthreads();
    for (int i = tid; i < 400 * 64; i += 256)
        atomicAdd(&g_upd[(i >> 6) * Dd + d0 + (i & 63)], acc[i]);
}

// ---------------- protos_new = l2norm(0.99*protos + 0.01*upd); fp32 + bf16 ------
__global__ void pnew_kernel(const float* __restrict__ protos) {
    int k = blockIdx.x;
    int tid = threadIdx.x;  // 128
    float v[4];
    float ss = 0.f;
#pragma unroll
    for (int j = 0; j < 4; j++) {
        int di = tid + 128 * j;
        float x = 0.99f * protos[k * Dd + di] + 0.01f * g_upd[k * Dd + di];
        v[j] = x;
        ss += x * x;
    }
    __shared__ float red[4];
#pragma unroll
    for (int o = 16; o; o >>= 1) ss += __shfl_xor_sync(0xffffffffu, ss, o);
    if ((tid & 31) == 0) red[tid >> 5] = ss;
    __syncthreads();
    float tot = red[0] + red[1] + red[2] + red[3];
    float inv = 1.f / fmaxf(sqrtf(tot), 1e-12f);
#pragma unroll
    for (int j = 0; j < 4; j++) {
        float y = v[j] * inv;
        g_pn[k * Dd + tid + 128 * j] = y;
        g_pbf[k * Dd + tid + 128 * j] = __float2bfloat16(y);
    }
}

// ---------------- small SIMT GEMM for adc = pn @ pn.T (400x400x512) ----------
__global__ void __launch_bounds__(256) adc_gemm(const float* __restrict__ A,
                                                const float* __restrict__ Bm,
                                                float* __restrict__ Cb, int Mr, int Nc)
{
    __shared__ float As[16][128];
    __shared__ float Bs[16][64];
    const int tid = threadIdx.x;
    const int bm = blockIdx.y * 128;
    const int bn = blockIdx.x * 64;
    const int tx = tid & 15;
    const int ty = tid >> 4;

    float acc[8][4];
#pragma unroll
    for (int i = 0; i < 8; i++)
#pragma unroll
        for (int j = 0; j < 4; j++) acc[i][j] = 0.f;

    const int alr = tid >> 1, alc = (tid & 1) * 8;
    const int blr = tid >> 2, blc = (tid & 3) * 4;
    const bool arow_ok = (bm + alr) < Mr;
    const bool brow_ok = (bn + blr) < Nc;
    const float* Aptr = A + (size_t)(bm + alr) * Dd + alc;
    const float* Bptr = Bm + (size_t)(bn + blr) * Dd + blc;

    for (int dk = 0; dk < Dd; dk += 16) {
        float4 a0 = {0,0,0,0}, a1 = {0,0,0,0}, b0 = {0,0,0,0};
        if (arow_ok) {
            a0 = *(const float4*)(Aptr + dk);
            a1 = *(const float4*)(Aptr + dk + 4);
        }
        if (brow_ok) b0 = *(const float4*)(Bptr + dk);
        As[alc + 0][alr] = a0.x; As[alc + 1][alr] = a0.y;
        As[alc + 2][alr] = a0.z; As[alc + 3][alr] = a0.w;
        As[alc + 4][alr] = a1.x; As[alc + 5][alr] = a1.y;
        As[alc + 6][alr] = a1.z; As[alc + 7][alr] = a1.w;
        Bs[blc + 0][blr] = b0.x; Bs[blc + 1][blr] = b0.y;
        Bs[blc + 2][blr] = b0.z; Bs[blc + 3][blr] = b0.w;
        __syncthreads();
#pragma unroll
        for (int dd = 0; dd < 16; dd++) {
            float4 av0 = *(const float4*)&As[dd][ty * 8];
            float4 av1 = *(const float4*)&As[dd][ty * 8 + 4];
            float4 bv  = *(const float4*)&Bs[dd][tx * 4];
            float ar[8] = {av0.x, av0.y, av0.z, av0.w, av1.x, av1.y, av1.z, av1.w};
            float br[4] = {bv.x, bv.y, bv.z, bv.w};
#pragma unroll
            for (int i = 0; i < 8; i++)
#pragma unroll
                for (int j = 0; j < 4; j++)
                    acc[i][j] = fmaf(ar[i], br[j], acc[i][j]);
        }
        __syncthreads();
    }
#pragma unroll
    for (int i = 0; i < 8; i++) {
        int n = bm + ty * 8 + i;
        if (n >= Mr) continue;
#pragma unroll
        for (int j = 0; j < 4; j++) {
            int k = bn + tx * 4 + j;
            if (k < Nc) Cb[(size_t)n * Kk + k] = acc[i][j];
        }
    }
}

// ---------------- proto contrast: one block per proto row ----------------
__global__ void pcon_kernel() {
    int k = blockIdx.x;
    int tid = threadIdx.x;  // 128
    const float* row = g_adc + k * Kk;
    __shared__ float rbuf[4];
    __shared__ float mxs;

    float mx = -1e30f;
    for (int j = tid; j < Kk; j += 128) mx = fmaxf(mx, 2.f * row[j]);
#pragma unroll
    for (int o = 16; o; o >>= 1) mx = fmaxf(mx, __shfl_xor_sync(0xffffffffu, mx, o));
    if ((tid & 31) == 0) rbuf[tid >> 5] = mx;
    __syncthreads();
    if (tid == 0) mxs = fmaxf(fmaxf(rbuf[0], rbuf[1]), fmaxf(rbuf[2], rbuf[3]));
    __syncthreads();
    mx = mxs;

    float se = 0.f, pp = 0.f;
    int cls = k % 100;
    for (int j = tid; j < Kk; j += 128) {
        float lg = 2.f * row[j] - mx;
        if (j != k) {
            se += __expf(lg);
            if (j % 100 == cls) pp += lg;
        }
    }
#pragma unroll
    for (int o = 16; o; o >>= 1) {
        se += __shfl_xor_sync(0xffffffffu, se, o);
        pp += __shfl_xor_sync(0xffffffffu, pp, o);
    }
    __shared__ float sbuf[4], pbuf[4];
    if ((tid & 31) == 0) { sbuf[tid >> 5] = se; pbuf[tid >> 5] = pp; }
    __syncthreads();
    if (tid == 0) {
        float sT = sbuf[0] + sbuf[1] + sbuf[2] + sbuf[3];
        float pT = pbuf[0] + pbuf[1] + pbuf[2] + pbuf[3];
        atomicAdd(&g_pconsum, pT * (1.f / 3.f) - logf(sT));
    }
}

// ---------------- final per-sample loss ----------------
__global__ void final_kernel(const int* __restrict__ labels,
                             const float* __restrict__ rs_in,
                             float* __restrict__ out) {
    int n = blockIdx.x * blockDim.x + threadIdx.x;
    if (n >= Nn) return;
    int l = labels[n];
    float4 cc = *(const float4*)&g_c4[n * 4];
    float cv[4] = {cc.x, cc.y, cc.z, cc.w};
    float num = 0.f, den = 0.f;
#pragma unroll
    for (int p = 0; p < 4; p++) {
        float c = cv[p];
        float q = mk_alpha(rs_in[l + 100 * p]) * __expf(20.f * c);
        num += q * (10.f * c);
        den += q;
    }
    float pos = num / fmaxf(den, 1e-30f);
    float neg = logf(g_negsum[n]);
    float pcon = -g_pconsum * (1.f / 400.f);
    out[n] = -(pos - neg) + pcon;
}

// ---------------- launch ----------------
extern "C" void kernel_launch(void* const* d_in, const int* in_sizes, int n_in,
                              void* d_out, int out_size) {
    const float* feats  = (const float*)d_in[0];
    const float* protos = (const float*)d_in[1];
    const int*   labels = (const int*)d_in[2];
    float* out = (float*)d_out;

    __nv_bfloat16* pE;
    float *pPN, *pADC, *pRS;
    cudaGetSymbolAddress((void**)&pE,  g_E);
    cudaGetSymbolAddress((void**)&pPN, g_pn);
    cudaGetSymbolAddress((void**)&pADC, g_adc);
    cudaGetSymbolAddress((void**)&pRS, g_rs);

    const int SMEM_SCATTER = (400 * 64 + 400) * 4;
    cudaFuncSetAttribute(scatter_kernel, cudaFuncAttributeMaxDynamicSharedMemorySize,
                         SMEM_SCATTER);
    const int TG_SMEM = 64 * 1040 + 3 * 11520 + 320;   // 101440
    cudaFuncSetAttribute(tgemm_kernel<1>, cudaFuncAttributeMaxDynamicSharedMemorySize, TG_SMEM);
    cudaFuncSetAttribute(tgemm_kernel<2>, cudaFuncAttributeMaxDynamicSharedMemorySize, TG_SMEM);

    init_kernel<<<(Kk * Dd + 255) / 256, 256>>>();
    convB_kernel<<<(Kk * Dd / 4 + 255) / 256, 256>>>(protos);

    const int NB = (Nn + 63) / 64;   // 1563

    // ---------- phase 1: E1 = exp(20*feats@protos^T), rowsum -> rs0, e4 ----------
    tgemm_kernel<1><<<NB, 256, TG_SMEM>>>(feats, labels, pRS + 0 * Kk);
    sink_pass<<<(Nn + 63) / 64, 256>>>(pE, pRS + 0 * Kk, pRS + 1 * Kk);
    sink_pass<<<(Nn + 63) / 64, 256>>>(pE, pRS + 1 * Kk, pRS + 2 * Kk);

    coeff_kernel<<<(Nn + 255) / 256, 256>>>(labels, pRS + 2 * Kk);
    {
        dim3 gs(8, 64);
        scatter_kernel<<<gs, 256, SMEM_SCATTER>>>(feats, labels, 64);
    }
    pnew_kernel<<<Kk, 128>>>(protos);   // writes g_pn (fp32) + g_pbf (bf16)

    // ---------- phase 2: E2, c4, negsum vs protos_new ----------
    tgemm_kernel<2><<<NB, 256, TG_SMEM>>>(feats, labels, pRS + 3 * Kk);
    sink_pass<<<(Nn + 63) / 64, 256>>>(pE, pRS + 3 * Kk, pRS + 4 * Kk);
    sink_pass<<<(Nn + 63) / 64, 256>>>(pE, pRS + 4 * Kk, pRS + 5 * Kk);

    // ---------- proto contrast ----------
    {
        dim3 ga((Kk + 63) / 64, (Kk + 127) / 128);
        adc_gemm<<<ga, 256>>>(pPN, pPN, pADC, Kk, Kk);
    }
    pcon_kernel<<<Kk, 128>>>();

    final_kernel<<<(Nn + 255) / 256, 256>>>(labels, pRS + 5 * Kk, out);
}

// round 17
// speedup vs baseline: 1.1579x; 1.0939x over previous
#include <cuda_runtime.h>
#include <cuda_bf16.h>
#include <math.h>
#include <stdint.h>

#define Nn 100000
#define Dd 512
#define Kk 400

// ---------------- scratch (device globals; no allocation allowed) ----------------
__device__ __nv_bfloat16 g_E[(size_t)Nn * Kk];  // exp(C/eps), bf16 (80MB)
__device__ float g_rs[6 * Kk];             // ping-pong rowsum buffers
__device__ float g_w2[Kk];
__device__ float g_coeff[Nn * 4];
__device__ float g_upd[Kk * Dd];
__device__ float g_pn[Kk * Dd];
__device__ __nv_bfloat16 g_pbf[Kk * Dd];   // bf16 B operand (protos, then protos_new)
__device__ float g_negsum[Nn];
__device__ float g_adc[Kk * Kk];
__device__ float g_e4[Nn * 4];             // phase1 E at the 4 class protos (fp32)
__device__ float g_c4[Nn * 4];             // phase2 raw cosine at the 4 class protos
__device__ float g_pconsum;

__device__ __forceinline__ uint32_t pack2(float lo, float hi) {
    uint32_t r;
    asm("cvt.rn.bf16x2.f32 %0, %1, %2;" : "=r"(r) : "f"(hi), "f"(lo));
    return r;
}
__device__ __forceinline__ float mk_alpha(float rs) {
    return 1.f / (400.f * fmaxf(rs, 1e-12f));
}
__device__ __forceinline__ float bf_lo(uint32_t u) { return __uint_as_float(u << 16); }
__device__ __forceinline__ float bf_hi(uint32_t u) { return __uint_as_float(u & 0xffff0000u); }

// ---------------- init ----------------
__global__ void init_kernel() {
    int i = blockIdx.x * blockDim.x + threadIdx.x;
    if (i < Kk * Dd) g_upd[i] = 0.f;
    if (i < Nn) g_negsum[i] = 0.f;
    if (i < 6 * Kk) g_rs[i] = 0.f;
    if (i < Kk) g_w2[i] = 0.f;
    if (i == 0) g_pconsum = 0.f;
}

// ---------------- fp32 -> bf16 B pre-convert ----------------
__global__ void convB_kernel(const float* __restrict__ src) {
    int i = blockIdx.x * blockDim.x + threadIdx.x;
    if (i < Kk * Dd / 4) {
        float4 v = ((const float4*)src)[i];
        reinterpret_cast<uint2*>(g_pbf)[i] = make_uint2(pack2(v.x, v.y), pack2(v.z, v.w));
    }
}

// dummy launch-slot filler so the ncu capture window lands on tgemm
__global__ void dummy_kernel() {}

// ---------------- A-resident bf16 HMMA GEMM + fused epilogue ----------------
// C[n,k] = sum_d A[n,d]*B[k,d]. BM=64 rows/CTA resident in smem (bf16), 2 CTAs/SM.
// Single 40-chunk pipeline (5 N-tiles x 8 K-chunks), B via cp.async 3-stage;
// epilogue per N-tile overlaps with next tile's loads. Coalesced E store via smem.
template <int PHASE>
__global__ void __launch_bounds__(256, 2) tgemm_kernel(
    const float* __restrict__ A, const int* __restrict__ labels,
    float* __restrict__ rowsum_out)
{
    constexpr int BM  = 64;
    constexpr int AST = 1040;             // A smem row stride
    constexpr int BST = 144;              // B smem row stride
    constexpr int ASZ = BM * AST;         // 66560
    constexpr int BBUF = 80 * BST;        // 11520
    constexpr int EST = 176;              // E staging row stride (80*2 + 16, 16B-aligned)

    extern __shared__ char smc[];
    char* smA = smc;
    char* smE = smc + ASZ + 3 * BBUF;                 // 64*176 = 11264
    float* colacc = (float*)(smc + ASZ + 3 * BBUF + 64 * EST);

    const uint32_t sAu = (uint32_t)__cvta_generic_to_shared(smA);
    const uint32_t sBu = sAu + ASZ;

    const int tid = threadIdx.x;
    const int bm = blockIdx.x * BM;
    const int lane = tid & 31, wid = tid >> 5;
    const int wm = wid >> 1, wn = wid & 1;

    // ---- load + convert A tile: 64 x 512 fp32 -> bf16 smem (resident) ----
#pragma unroll 4
    for (int it = 0; it < 16; it++) {
        int slot = tid + 256 * it;
        int row = slot >> 6, c = slot & 63;
        bool okr = (bm + row) < Nn;
        const float* src = A + (size_t)(bm + row) * Dd + c * 8;
        float4 v0 = okr ? *(const float4*)src : make_float4(0.f, 0.f, 0.f, 0.f);
        float4 v1 = okr ? *(const float4*)(src + 4) : make_float4(0.f, 0.f, 0.f, 0.f);
        *(uint4*)(smA + row * AST + c * 16) =
            make_uint4(pack2(v0.x, v0.y), pack2(v0.z, v0.w),
                       pack2(v1.x, v1.y), pack2(v1.z, v1.w));
    }

    // per-thread epilogue row info
    int rr[2], lb[2];
    bool ok[2];
#pragma unroll
    for (int h = 0; h < 2; h++) {
        int r = bm + wm * 16 + h * 8 + (lane >> 2);
        rr[h] = r; ok[h] = r < Nn;
        lb[h] = ok[h] ? labels[r] : -1;
    }
    float nacc[2] = {0.f, 0.f};

    // chunk g -> nt = g>>3 (N tile), kc = g&7 (K chunk), stage = g%3
    auto ldgB = [&](int g) {
        int nt = g >> 3, kc = g & 7, st = g % 3;
#pragma unroll
        for (int it = 0; it < 3; it++) {
            int slot = tid + 256 * it;
            if (slot < 640) {
                int row = slot >> 3, c = slot & 7;
                uint32_t dst = sBu + st * BBUF + row * BST + c * 16;
                const __nv_bfloat16* src =
                    g_pbf + (size_t)(nt * 80 + row) * Dd + kc * 64 + c * 8;
                asm volatile("cp.async.cg.shared.global [%0], [%1], 16;"
                             :: "r"(dst), "l"(src));
            }
        }
        asm volatile("cp.async.commit_group;" ::: "memory");
    };

    float acc[5][4];

    auto compute = [&](int g) {
        const int kc = g & 7;
        const uint32_t sBb = sBu + (g % 3) * BBUF;
#pragma unroll
        for (int kf = 0; kf < 4; kf++) {
            const int kk = kc * 4 + kf;
            uint32_t af[4];
            uint32_t ad = sAu + (wm * 16 + (lane & 15)) * AST + kk * 32 + (lane >> 4) * 16;
            asm volatile("ldmatrix.sync.aligned.m8n8.x4.shared.b16 {%0,%1,%2,%3},[%4];"
                : "=r"(af[0]), "=r"(af[1]), "=r"(af[2]), "=r"(af[3]) : "r"(ad));
            uint32_t bf[5][2];
            {
                const int g2 = lane >> 3;
                uint32_t bd = sBb + (wn * 40 + (0 + (g2 >> 1)) * 8 + (lane & 7)) * BST
                            + kf * 32 + (g2 & 1) * 16;
                asm volatile("ldmatrix.sync.aligned.m8n8.x4.shared.b16 {%0,%1,%2,%3},[%4];"
                    : "=r"(bf[0][0]), "=r"(bf[0][1]), "=r"(bf[1][0]), "=r"(bf[1][1])
                    : "r"(bd));
                uint32_t bd2 = sBb + (wn * 40 + (2 + (g2 >> 1)) * 8 + (lane & 7)) * BST
                             + kf * 32 + (g2 & 1) * 16;
                asm volatile("ldmatrix.sync.aligned.m8n8.x4.shared.b16 {%0,%1,%2,%3},[%4];"
                    : "=r"(bf[2][0]), "=r"(bf[2][1]), "=r"(bf[3][0]), "=r"(bf[3][1])
                    : "r"(bd2));
                const int lq = lane & 15;
                uint32_t bd3 = sBb + (wn * 40 + 32 + (lq & 7)) * BST
                             + kf * 32 + (lq >> 3) * 16;
                asm volatile("ldmatrix.sync.aligned.m8n8.x2.shared.b16 {%0,%1},[%2];"
                    : "=r"(bf[4][0]), "=r"(bf[4][1]) : "r"(bd3));
            }
#pragma unroll
            for (int j = 0; j < 5; j++)
                asm volatile(
                    "mma.sync.aligned.m16n8k16.row.col.f32.bf16.bf16.f32 "
                    "{%0,%1,%2,%3},{%4,%5,%6,%7},{%8,%9},{%0,%1,%2,%3};"
                    : "+f"(acc[j][0]), "+f"(acc[j][1]), "+f"(acc[j][2]), "+f"(acc[j][3])
                    : "r"(af[0]), "r"(af[1]), "r"(af[2]), "r"(af[3]),
                      "r"(bf[j][0]), "r"(bf[j][1]));
        }
    };

    auto epilogue = [&](int nt) {
        for (int i = tid; i < 80; i += 256) colacc[i] = 0.f;
        __syncthreads();
#pragma unroll
        for (int j = 0; j < 5; j++) {
            const int ccol = wn * 40 + j * 8 + (lane & 3) * 2;   // 0..79
            const int c0 = nt * 80 + ccol;
            const int km = c0 % 100;
            const int kd = c0 / 100;
            float cs0 = 0.f, cs1 = 0.f;
#pragma unroll
            for (int h = 0; h < 2; h++) {
                float v0 = acc[j][2 * h], v1 = acc[j][2 * h + 1];
                float e0, e1;
                if (PHASE == 1) {
                    e0 = __expf(20.f * v0); e1 = __expf(20.f * v1);
                } else {
                    float x0 = __expf(10.f * v0), x1 = __expf(10.f * v1);
                    if (ok[h]) nacc[h] += x0 + x1;
                    e0 = x0 * x0; e1 = x1 * x1;
                }
                if (ok[h]) {
                    int row = wm * 16 + h * 8 + (lane >> 2);
                    *(uint32_t*)(smE + row * EST + ccol * 2) = pack2(e0, e1);
                    if (PHASE == 1) {
                        if (km == lb[h])     g_e4[rr[h] * 4 + kd] = e0;
                        if (km + 1 == lb[h]) g_e4[rr[h] * 4 + kd] = e1;
                    } else {
                        if (km == lb[h])     g_c4[rr[h] * 4 + kd] = v0;
                        if (km + 1 == lb[h]) g_c4[rr[h] * 4 + kd] = v1;
                    }
                    cs0 += e0; cs1 += e1;
                }
            }
#pragma unroll
            for (int o = 4; o <= 16; o <<= 1) {
                cs0 += __shfl_xor_sync(0xffffffffu, cs0, o);
                cs1 += __shfl_xor_sync(0xffffffffu, cs1, o);
            }
            if (lane < 4) {
                atomicAdd(&colacc[wn * 40 + j * 8 + lane * 2], cs0);
                atomicAdd(&colacc[wn * 40 + j * 8 + lane * 2 + 1], cs1);
            }
        }
        __syncthreads();
        // coalesced E writeout: 64 rows x 160B (both smem and gmem 16B-aligned)
        for (int i = tid; i < 640; i += 256) {
            int row = i / 10;
            int c = i - row * 10;
            int r = bm + row;
            if (r < Nn)
                *(uint4*)((char*)g_E + (size_t)r * 800 + nt * 160 + c * 16) =
                    *(uint4*)(smE + row * EST + c * 16);
        }
        for (int i = tid; i < 80; i += 256) atomicAdd(&rowsum_out[nt * 80 + i], colacc[i]);
        __syncthreads();
    };

    // ---- pipelined mainloop over 40 chunks ----
    ldgB(0); ldgB(1);
#pragma unroll 1
    for (int g = 0; g < 40; g++) {
        if ((g & 7) == 0) {
#pragma unroll
            for (int j = 0; j < 5; j++)
#pragma unroll
                for (int q = 0; q < 4; q++) acc[j][q] = 0.f;
        }
        if (g == 39) asm volatile("cp.async.wait_group 0;" ::: "memory");
        else         asm volatile("cp.async.wait_group 1;" ::: "memory");
        __syncthreads();
        if (g + 2 < 40) ldgB(g + 2);
        compute(g);
        if ((g & 7) == 7) epilogue(g >> 3);
    }

    if (PHASE == 2) {
#pragma unroll
        for (int h = 0; h < 2; h++) {
            float v = nacc[h];
            v += __shfl_xor_sync(0xffffffffu, v, 1);
            v += __shfl_xor_sync(0xffffffffu, v, 2);
            if ((lane & 3) == 0 && ok[h]) atomicAdd(&g_negsum[rr[h]], v);
        }
    }
}

// ---------------- fused Sinkhorn pass over bf16 E (alphas in registers) ----------
__global__ void __launch_bounds__(256) sink_pass(const __nv_bfloat16* __restrict__ E,
                                                 const float* __restrict__ rs_in,
                                                 float* __restrict__ rs_out) {
    __shared__ float s_acc[Kk];
    for (int i = threadIdx.x; i < Kk; i += 256) s_acc[i] = 0.f;
    __syncthreads();

    const int lane = threadIdx.x & 31;
    const int warp = threadIdx.x >> 5;
    const int n0 = (blockIdx.x * 8 + warp) * 8;

    // per-thread fixed columns: (lane+32j)*4 + t  -> preload alphas into registers
    float al[4][4];
    float racc[4][4];
#pragma unroll
    for (int j = 0; j < 4; j++) {
        int idx = lane + 32 * j;
        bool valid = (j < 3) || (lane < 4);
        float4 r4 = valid ? ((const float4*)rs_in)[idx] : make_float4(1.f, 1.f, 1.f, 1.f);
        al[j][0] = mk_alpha(r4.x); al[j][1] = mk_alpha(r4.y);
        al[j][2] = mk_alpha(r4.z); al[j][3] = mk_alpha(r4.w);
#pragma unroll
        for (int t = 0; t < 4; t++) racc[j][t] = 0.f;
    }

#pragma unroll 1
    for (int r = 0; r < 8; r++) {
        int n = n0 + r;
        if (n >= Nn) break;
        const uint2* row = (const uint2*)(E + (size_t)n * Kk);
        uint2 u[4];
        float ev[4][4];
        float s = 0.f;
#pragma unroll
        for (int j = 0; j < 4; j++) {
            int idx = lane + 32 * j;
            bool valid = (j < 3) || (lane < 4);
            u[j] = valid ? row[idx] : make_uint2(0u, 0u);
            ev[j][0] = bf_lo(u[j].x); ev[j][1] = bf_hi(u[j].x);
            ev[j][2] = bf_lo(u[j].y); ev[j][3] = bf_hi(u[j].y);
#pragma unroll
            for (int t = 0; t < 4; t++)
                s = fmaf(ev[j][t], al[j][t], s);
        }
#pragma unroll
        for (int o = 16; o; o >>= 1) s += __shfl_xor_sync(0xffffffffu, s, o);
        float beta = 1.f / ((float)Nn * fmaxf(s, 1e-30f));
#pragma unroll
        for (int j = 0; j < 4; j++)
#pragma unroll
            for (int t = 0; t < 4; t++)
                racc[j][t] = fmaf(ev[j][t], beta, racc[j][t]);
    }
#pragma unroll
    for (int j = 0; j < 4; j++) {
        int idx = lane + 32 * j;
        if ((j < 3) || (lane < 4)) {
#pragma unroll
            for (int t = 0; t < 4; t++)
                atomicAdd(&s_acc[idx * 4 + t], racc[j][t]);
        }
    }
    __syncthreads();
    for (int i = threadIdx.x; i < Kk; i += 256) atomicAdd(&rs_out[i], s_acc[i]);
}

// ---------------- per-sample transport coeffs + column sums w2 ----------------
__global__ void coeff_kernel(const int* __restrict__ labels,
                             const float* __restrict__ rs_in) {
    __shared__ float sacc[Kk];
    for (int i = threadIdx.x; i < Kk; i += blockDim.x) sacc[i] = 0.f;
    __syncthreads();
    int n = blockIdx.x * blockDim.x + threadIdx.x;
    int l = 0;
    float c4[4] = {0.f, 0.f, 0.f, 0.f};
    if (n < Nn) {
        l = labels[n];
        float q[4], s = 0.f;
        float4 e4 = *(const float4*)&g_e4[n * 4];
        float ev[4] = {e4.x, e4.y, e4.z, e4.w};
#pragma unroll
        for (int p = 0; p < 4; p++) {
            q[p] = mk_alpha(rs_in[l + 100 * p]) * ev[p];
            s += q[p];
        }
        float inv = 1.f / fmaxf(s, 1e-30f);
#pragma unroll
        for (int p = 0; p < 4; p++) {
            float c = q[p] * inv;
            c4[p] = c;
            g_coeff[n * 4 + p] = c;
        }
#pragma unroll
        for (int p = 0; p < 4; p++) atomicAdd(&sacc[l + 100 * p], c4[p]);
    }
    __syncthreads();
    for (int i = threadIdx.x; i < Kk; i += blockDim.x) atomicAdd(&g_w2[i], sacc[i]);
}

// ---------------- scatter: upd[k,d] += (coeff/w2[k]) * f[n,d] ----------------
__global__ void __launch_bounds__(256) scatter_kernel(const float* __restrict__ feats,
                                                      const int* __restrict__ labels,
                                                      int nchunks) {
    extern __shared__ float sm[];
    float* acc = sm;               // 400*64
    float* winv = sm + 400 * 64;   // 400
    const int tid = threadIdx.x;
    for (int i = tid; i < 400 * 64; i += 256) acc[i] = 0.f;
    for (int i = tid; i < Kk; i += 256) winv[i] = 1.f / fmaxf(g_w2[i], 1e-12f);
    __syncthreads();

    const int d = tid & 63;
    const int sub = tid >> 6;
    const int d0 = blockIdx.x * 64;
    const int CH = (Nn + nchunks - 1) / nchunks;
    const int nb = blockIdx.y * CH;
    const int ne = (nb + CH < Nn) ? (nb + CH) : Nn;

    int n = nb;
    for (; n + 1 < ne; n += 2) {
        int l0 = labels[n], l1 = labels[n + 1];
        float f0 = feats[(size_t)n * Dd + d0 + d];
        float f1 = feats[(size_t)(n + 1) * Dd + d0 + d];
        float q0 = g_coeff[n * 4 + sub];
        float q1 = g_coeff[(n + 1) * 4 + sub];
        int k0 = l0 + 100 * sub, k1 = l1 + 100 * sub;
        acc[k0 * 64 + d] += q0 * winv[k0] * f0;
        acc[k1 * 64 + d] += q1 * winv[k1] * f1;
    }
    if (n < ne) {
        int l = labels[n];
        float f = feats[(size_t)n * Dd + d0 + d];
        int k = l + 100 * sub;
        acc[k * 64 + d] += g_coeff[n * 4 + sub] * winv[k] * f;
    }
    __syncthreads();
    for (int i = tid; i < 400 * 64; i += 256)
        atomicAdd(&g_upd[(i >> 6) * Dd + d0 + (i & 63)], acc[i]);
}

// ---------------- protos_new = l2norm(0.99*protos + 0.01*upd); fp32 + bf16 ------
__global__ void pnew_kernel(const float* __restrict__ protos) {
    int k = blockIdx.x;
    int tid = threadIdx.x;  // 128
    float v[4];
    float ss = 0.f;
#pragma unroll
    for (int j = 0; j < 4; j++) {
        int di = tid + 128 * j;
        float x = 0.99f * protos[k * Dd + di] + 0.01f * g_upd[k * Dd + di];
        v[j] = x;
        ss += x * x;
    }
    __shared__ float red[4];
#pragma unroll
    for (int o = 16; o; o >>= 1) ss += __shfl_xor_sync(0xffffffffu, ss, o);
    if ((tid & 31) == 0) red[tid >> 5] = ss;
    __syncthreads();
    float tot = red[0] + red[1] + red[2] + red[3];
    float inv = 1.f / fmaxf(sqrtf(tot), 1e-12f);
#pragma unroll
    for (int j = 0; j < 4; j++) {
        float y = v[j] * inv;
        g_pn[k * Dd + tid + 128 * j] = y;
        g_pbf[k * Dd + tid + 128 * j] = __float2bfloat16(y);
    }
}

// ---------------- small SIMT GEMM for adc = pn @ pn.T (400x400x512) ----------
__global__ void __launch_bounds__(256) adc_gemm(const float* __restrict__ A,
                                                const float* __restrict__ Bm,
                                                float* __restrict__ Cb, int Mr, int Nc)
{
    __shared__ float As[16][128];
    __shared__ float Bs[16][64];
    const int tid = threadIdx.x;
    const int bm = blockIdx.y * 128;
    const int bn = blockIdx.x * 64;
    const int tx = tid & 15;
    const int ty = tid >> 4;

    float acc[8][4];
#pragma unroll
    for (int i = 0; i < 8; i++)
#pragma unroll
        for (int j = 0; j < 4; j++) acc[i][j] = 0.f;

    const int alr = tid >> 1, alc = (tid & 1) * 8;
    const int blr = tid >> 2, blc = (tid & 3) * 4;
    const bool arow_ok = (bm + alr) < Mr;
    const bool brow_ok = (bn + blr) < Nc;
    const float* Aptr = A + (size_t)(bm + alr) * Dd + alc;
    const float* Bptr = Bm + (size_t)(bn + blr) * Dd + blc;

    for (int dk = 0; dk < Dd; dk += 16) {
        float4 a0 = {0,0,0,0}, a1 = {0,0,0,0}, b0 = {0,0,0,0};
        if (arow_ok) {
            a0 = *(const float4*)(Aptr + dk);
            a1 = *(const float4*)(Aptr + dk + 4);
        }
        if (brow_ok) b0 = *(const float4*)(Bptr + dk);
        As[alc + 0][alr] = a0.x; As[alc + 1][alr] = a0.y;
        As[alc + 2][alr] = a0.z; As[alc + 3][alr] = a0.w;
        As[alc + 4][alr] = a1.x; As[alc + 5][alr] = a1.y;
        As[alc + 6][alr] = a1.z; As[alc + 7][alr] = a1.w;
        Bs[blc + 0][blr] = b0.x; Bs[blc + 1][blr] = b0.y;
        Bs[blc + 2][blr] = b0.z; Bs[blc + 3][blr] = b0.w;
        __syncthreads();
#pragma unroll
        for (int dd = 0; dd < 16; dd++) {
            float4 av0 = *(const float4*)&As[dd][ty * 8];
            float4 av1 = *(const float4*)&As[dd][ty * 8 + 4];
            float4 bv  = *(const float4*)&Bs[dd][tx * 4];
            float ar[8] = {av0.x, av0.y, av0.z, av0.w, av1.x, av1.y, av1.z, av1.w};
            float br[4] = {bv.x, bv.y, bv.z, bv.w};
#pragma unroll
            for (int i = 0; i < 8; i++)
#pragma unroll
                for (int j = 0; j < 4; j++)
                    acc[i][j] = fmaf(ar[i], br[j], acc[i][j]);
        }
        __syncthreads();
    }
#pragma unroll
    for (int i = 0; i < 8; i++) {
        int n = bm + ty * 8 + i;
        if (n >= Mr) continue;
#pragma unroll
        for (int j = 0; j < 4; j++) {
            int k = bn + tx * 4 + j;
            if (k < Nc) Cb[(size_t)n * Kk + k] = acc[i][j];
        }
    }
}

// ---------------- proto contrast: one block per proto row ----------------
__global__ void pcon_kernel() {
    int k = blockIdx.x;
    int tid = threadIdx.x;  // 128
    const float* row = g_adc + k * Kk;
    __shared__ float rbuf[4];
    __shared__ float mxs;

    float mx = -1e30f;
    for (int j = tid; j < Kk; j += 128) mx = fmaxf(mx, 2.f * row[j]);
#pragma unroll
    for (int o = 16; o; o >>= 1) mx = fmaxf(mx, __shfl_xor_sync(0xffffffffu, mx, o));
    if ((tid & 31) == 0) rbuf[tid >> 5] = mx;
    __syncthreads();
    if (tid == 0) mxs = fmaxf(fmaxf(rbuf[0], rbuf[1]), fmaxf(rbuf[2], rbuf[3]));
    __syncthreads();
    mx = mxs;

    float se = 0.f, pp = 0.f;
    int cls = k % 100;
    for (int j = tid; j < Kk; j += 128) {
        float lg = 2.f * row[j] - mx;
        if (j != k) {
            se += __expf(lg);
            if (j % 100 == cls) pp += lg;
        }
    }
#pragma unroll
    for (int o = 16; o; o >>= 1) {
        se += __shfl_xor_sync(0xffffffffu, se, o);
        pp += __shfl_xor_sync(0xffffffffu, pp, o);
    }
    __shared__ float sbuf[4], pbuf[4];
    if ((tid & 31) == 0) { sbuf[tid >> 5] = se; pbuf[tid >> 5] = pp; }
    __syncthreads();
    if (tid == 0) {
        float sT = sbuf[0] + sbuf[1] + sbuf[2] + sbuf[3];
        float pT = pbuf[0] + pbuf[1] + pbuf[2] + pbuf[3];
        atomicAdd(&g_pconsum, pT * (1.f / 3.f) - logf(sT));
    }
}

// ---------------- final per-sample loss ----------------
__global__ void final_kernel(const int* __restrict__ labels,
                             const float* __restrict__ rs_in,
                             float* __restrict__ out) {
    int n = blockIdx.x * blockDim.x + threadIdx.x;
    if (n >= Nn) return;
    int l = labels[n];
    float4 cc = *(const float4*)&g_c4[n * 4];
    float cv[4] = {cc.x, cc.y, cc.z, cc.w};
    float num = 0.f, den = 0.f;
#pragma unroll
    for (int p = 0; p < 4; p++) {
        float c = cv[p];
        float q = mk_alpha(rs_in[l + 100 * p]) * __expf(20.f * c);
        num += q * (10.f * c);
        den += q;
    }
    float pos = num / fmaxf(den, 1e-30f);
    float neg = logf(g_negsum[n]);
    float pcon = -g_pconsum * (1.f / 400.f);
    out[n] = -(pos - neg) + pcon;
}

// ---------------- launch ----------------
extern "C" void kernel_launch(void* const* d_in, const int* in_sizes, int n_in,
                              void* d_out, int out_size) {
    const float* feats  = (const float*)d_in[0];
    const float* protos = (const float*)d_in[1];
    const int*   labels = (const int*)d_in[2];
    float* out = (float*)d_out;

    __nv_bfloat16* pE;
    float *pPN, *pADC, *pRS;
    cudaGetSymbolAddress((void**)&pE,  g_E);
    cudaGetSymbolAddress((void**)&pPN, g_pn);
    cudaGetSymbolAddress((void**)&pADC, g_adc);
    cudaGetSymbolAddress((void**)&pRS, g_rs);

    const int SMEM_SCATTER = (400 * 64 + 400) * 4;
    cudaFuncSetAttribute(scatter_kernel, cudaFuncAttributeMaxDynamicSharedMemorySize,
                         SMEM_SCATTER);
    const int TG_SMEM = 64 * 1040 + 3 * 11520 + 64 * 176 + 320;   // 112704
    cudaFuncSetAttribute(tgemm_kernel<1>, cudaFuncAttributeMaxDynamicSharedMemorySize, TG_SMEM);
    cudaFuncSetAttribute(tgemm_kernel<2>, cudaFuncAttributeMaxDynamicSharedMemorySize, TG_SMEM);

    init_kernel<<<(Kk * Dd + 255) / 256, 256>>>();
    convB_kernel<<<(Kk * Dd / 4 + 255) / 256, 256>>>(protos);
    dummy_kernel<<<1, 32>>>();   // shift launch index so ncu window hits tgemm

    const int NB = (Nn + 63) / 64;   // 1563

    // ---------- phase 1: E1 = exp(20*feats@protos^T), rowsum -> rs0, e4 ----------
    tgemm_kernel<1><<<NB, 256, TG_SMEM>>>(feats, labels, pRS + 0 * Kk);
    sink_pass<<<(Nn + 63) / 64, 256>>>(pE, pRS + 0 * Kk, pRS + 1 * Kk);
    sink_pass<<<(Nn + 63) / 64, 256>>>(pE, pRS + 1 * Kk, pRS + 2 * Kk);

    coeff_kernel<<<(Nn + 255) / 256, 256>>>(labels, pRS + 2 * Kk);
    {
        dim3 gs(8, 64);
        scatter_kernel<<<gs, 256, SMEM_SCATTER>>>(feats, labels, 64);
    }
    pnew_kernel<<<Kk, 128>>>(protos);   // writes g_pn (fp32) + g_pbf (bf16)

    // ---------- phase 2: E2, c4, negsum vs protos_new ----------
    tgemm_kernel<2><<<NB, 256, TG_SMEM>>>(feats, labels, pRS + 3 * Kk);
    sink_pass<<<(Nn + 63) / 64, 256>>>(pE, pRS + 3 * Kk, pRS + 4 * Kk);
    sink_pass<<<(Nn + 63) / 64, 256>>>(pE, pRS + 4 * Kk, pRS + 5 * Kk);

    // ---------- proto contrast ----------
    {
        dim3 ga((Kk + 63) / 64, (Kk + 127) / 128);
        adc_gemm<<<ga, 256>>>(pPN, pPN, pADC, Kk, Kk);
    }
    pcon_kernel<<<Kk, 128>>>();

    final_kernel<<<(Nn + 255) / 256, 256>>>(labels, pRS + 5 * Kk, out);
}